// round 11
// baseline (speedup 1.0000x reference)
#include <cuda_runtime.h>

#define T_STEPS 50
#define BATCH   2048
#define D_IN    1156
#define H       128
#define OUT_N   10
#define KC      248          // Eigen kc (aarch64 default l1=16KB) -- verified exact

// Scratch: cur1[t][b][h] = (x[t,b,:] @ W1.T)[h]   (bias b1 added in scan)
__device__ float g_cur1[(size_t)T_STEPS * BATCH * H];  // 52.4 MB
// Per-timestep completion counters (16 GEMM tiles per timestep)
__device__ int g_cnt[T_STEPS];

__device__ __forceinline__ int ld_acquire_gpu(const int* p) {
    int v;
    asm volatile("ld.acquire.gpu.b32 %0, [%1];" : "=r"(v) : "l"(p) : "memory");
    return v;
}

// ---------------------------------------------------------------------------
// SGEMM emulating Eigen gebp (bit-exact, verified): KC=248 panels, each an
// ascending-k FMA chain per element, folded left-to-right in GMEM.
// 128x128 tile, BK=8, 256 threads, 8x8 micro-tile, double-buffered smem,
// 2 blocks/SM. At the FFMA issue floor (measured 844us). Signals g_cnt[t].
// ---------------------------------------------------------------------------
__global__ __launch_bounds__(256, 2)
void gemm_xw1(const float* __restrict__ A, const float* __restrict__ W, int M, int K) {
    const int BK = 8;
    __shared__ float As[2][BK][128];
    __shared__ float Bs[2][BK][128];

    int tid = threadIdx.x;
    int block_m = blockIdx.x * 128;
    int tx = tid & 15;
    int ty = tid >> 4;

    float acc[8][8];
#pragma unroll
    for (int i = 0; i < 8; i++)
#pragma unroll
        for (int j = 0; j < 8; j++) acc[i][j] = 0.f;

    int lRow = tid >> 1;
    int lCol = (tid & 1) * 4;
    const float* Aptr = A + (size_t)(block_m + lRow) * K;
    const float* Wptr = W + (size_t)lRow * K;

    const int NIT = (K + BK - 1) / BK;   // 145

    float4 av, wv;
    {   // fetch tile 0
        av = make_float4(0.f, 0.f, 0.f, 0.f);
        wv = make_float4(0.f, 0.f, 0.f, 0.f);
        if (lCol < K) {
            av = *(const float4*)(Aptr + lCol);
            wv = *(const float4*)(Wptr + lCol);
        }
        As[0][lCol + 0][lRow] = av.x; As[0][lCol + 1][lRow] = av.y;
        As[0][lCol + 2][lRow] = av.z; As[0][lCol + 3][lRow] = av.w;
        Bs[0][lCol + 0][lRow] = wv.x; Bs[0][lCol + 1][lRow] = wv.y;
        Bs[0][lCol + 2][lRow] = wv.z; Bs[0][lCol + 3][lRow] = wv.w;
    }
    __syncthreads();

    int panel_done = 0;
    float* cbase = g_cur1 + (size_t)(block_m + ty * 8) * H + tx * 8;

    for (int it = 0; it < NIT; it++) {
        int cur = it & 1;
        int nxt = cur ^ 1;

        if (it + 1 < NIT) {   // prefetch next tile while computing current
            int k0 = (it + 1) * BK;
            av = make_float4(0.f, 0.f, 0.f, 0.f);
            wv = make_float4(0.f, 0.f, 0.f, 0.f);
            if (k0 + lCol < K) {   // zero-pad tail; zeros are exact FMA no-ops
                av = *(const float4*)(Aptr + k0 + lCol);
                wv = *(const float4*)(Wptr + k0 + lCol);
            }
        }

#pragma unroll
        for (int kk = 0; kk < BK; kk++) {
            float ra[8], rb[8];
#pragma unroll
            for (int i = 0; i < 8; i++) ra[i] = As[cur][kk][ty * 8 + i];
#pragma unroll
            for (int j = 0; j < 8; j++) rb[j] = Bs[cur][kk][tx * 8 + j];
#pragma unroll
            for (int i = 0; i < 8; i++)
#pragma unroll
                for (int j = 0; j < 8; j++)
                    acc[i][j] = __fmaf_rn(ra[i], rb[j], acc[i][j]);
        }

        if (it + 1 < NIT) {
            As[nxt][lCol + 0][lRow] = av.x; As[nxt][lCol + 1][lRow] = av.y;
            As[nxt][lCol + 2][lRow] = av.z; As[nxt][lCol + 3][lRow] = av.w;
            Bs[nxt][lCol + 0][lRow] = wv.x; Bs[nxt][lCol + 1][lRow] = wv.y;
            Bs[nxt][lCol + 2][lRow] = wv.z; Bs[nxt][lCol + 3][lRow] = wv.w;
        }
        __syncthreads();

        // Eigen panel boundary: fold partial into C (gmem), left-to-right.
        int knext = (it + 1) * BK;
        if ((knext % KC) == 0 || knext >= K) {
            if (panel_done == 0) {
#pragma unroll
                for (int i = 0; i < 8; i++) {
                    float* crow = cbase + (size_t)i * H;
#pragma unroll
                    for (int j = 0; j < 8; j += 4)
                        *(float4*)(crow + j) = make_float4(acc[i][j], acc[i][j+1],
                                                           acc[i][j+2], acc[i][j+3]);
                }
            } else {
#pragma unroll
                for (int i = 0; i < 8; i++) {
                    float* crow = cbase + (size_t)i * H;
#pragma unroll
                    for (int j = 0; j < 8; j += 4) {
                        float4 c = *(float4*)(crow + j);
                        c.x = __fadd_rn(c.x, acc[i][j    ]);
                        c.y = __fadd_rn(c.y, acc[i][j + 1]);
                        c.z = __fadd_rn(c.z, acc[i][j + 2]);
                        c.w = __fadd_rn(c.w, acc[i][j + 3]);
                        *(float4*)(crow + j) = c;
                    }
                }
            }
            panel_done++;
#pragma unroll
            for (int i = 0; i < 8; i++)
#pragma unroll
                for (int j = 0; j < 8; j++) acc[i][j] = 0.f;
        }
    }

    // Signal: this tile (128 M-rows, all within one timestep) is complete.
    __threadfence();
    __syncthreads();
    if (tid == 0) atomicAdd(&g_cnt[block_m >> 11], 1);   // 2048 rows per t
}

// ---------------------------------------------------------------------------
// Dense-FMA LIF scan. 256 threads, 8 rows/block (2 groups x 4 rows), grid 256.
// Spikes stored as FLOATS in smem; rec/cur2 are dense ascending-j FMA chains
// with 0/1 multipliers -- bit-identical to the verified sparse-fadd chains
// (fma(1,v,a)=fadd(v,a); fma(0,v,a)=a; acc never -0). Static vectorized LDS,
// one __syncthreads per step, double-buffered spikes. Layer 2: one row/warp.
// ---------------------------------------------------------------------------
#define ROWS_PB 8
#define SCAN_THREADS 256
#define VSTRIDE 132                              // floats; 16B-aligned rows
#define V1S_ELEMS (128 * VSTRIDE)                // 16896
#define W2S_ELEMS (OUT_N * VSTRIDE)              // 1320
#define SF_ELEMS  (2 * ROWS_PB * VSTRIDE)        // 2112
#define SPK2_STRIDE 12
#define SPK2_ELEMS (2 * ROWS_PB * SPK2_STRIDE)   // 192
#define SCAN_SMEM_FLOATS (V1S_ELEMS + W2S_ELEMS + SF_ELEMS + SPK2_ELEMS)
#define SCAN_SMEM_BYTES (SCAN_SMEM_FLOATS * 4)

__global__ __launch_bounds__(SCAN_THREADS, 2)
void scan_kernel(const float* __restrict__ b1, const float* __restrict__ V1,
                 const float* __restrict__ bV1, const float* __restrict__ W2,
                 const float* __restrict__ b2, const float* __restrict__ V2,
                 const float* __restrict__ bV2, float* __restrict__ out) {
    extern __shared__ float smem[];
    float* V1s   = smem;                         // [h*132 + j] = V1[h][j]
    float* W2s   = smem + V1S_ELEMS;             // [o*132 + j]
    float* sf    = W2s + W2S_ELEMS;              // [(buf*8+lrow)*132 + h]
    float* sspk2 = sf + SF_ELEMS;                // [(buf*8+lrow)*12 + o]

    int tid  = threadIdx.x;
    int h    = tid & 127;
    int g    = tid >> 7;                         // group 0/1 -> rows 4g..4g+3
    int wid  = tid >> 5;                         // warp 0..7 -> layer-2 row wid
    int lane = tid & 31;
    int base = blockIdx.x * ROWS_PB;

    for (int idx = tid; idx < 128 * 128; idx += SCAN_THREADS)
        V1s[(idx >> 7) * VSTRIDE + (idx & 127)] = V1[idx];
    for (int idx = tid; idx < OUT_N * 128; idx += SCAN_THREADS)
        W2s[(idx >> 7) * VSTRIDE + (idx & 127)] = W2[idx];
    for (int idx = tid; idx < SF_ELEMS; idx += SCAN_THREADS) sf[idx] = 0.f;
    if (tid < SPK2_ELEMS) sspk2[tid] = 0.f;

    // Layer-2 per-lane constants (lanes 0..9 of each warp)
    float V2row[OUT_N];
    float b2o = 0.f, bV2o = 0.f, mem2 = 0.f;
    if (lane < OUT_N) {
#pragma unroll
        for (int p = 0; p < OUT_N; p++) V2row[p] = V2[lane * OUT_N + p];
        b2o = b2[lane]; bV2o = bV2[lane];
    }

    float b1h  = b1[h];
    float bV1h = bV1[h];
    float mem1[4] = {0.f, 0.f, 0.f, 0.f};
    const float* gp[4];
#pragma unroll
    for (int k = 0; k < 4; k++)
        gp[k] = g_cur1 + (size_t)(base + 4 * g + k) * H + h;
    float* ob = out + (size_t)(base + wid) * OUT_N + lane;
    const float* vrow = V1s + h * VSTRIDE;
    __syncthreads();

    for (int t = 0; t < T_STEPS; t++) {
        int pw = t & 1;
        int pr = pw ^ 1;

        // ---- layer 1 rec: dense ascending-j FMA chains, 4 rows share v4 ----
        float r0 = 0.f, r1 = 0.f, r2 = 0.f, r3 = 0.f;
        const float* s0 = sf + (pr * ROWS_PB + 4 * g) * VSTRIDE;
#pragma unroll 8
        for (int c = 0; c < 32; c++) {
            float4 v = *(const float4*)(vrow + 4 * c);
            float4 a0 = *(const float4*)(s0 + 4 * c);
            float4 a1 = *(const float4*)(s0 + VSTRIDE + 4 * c);
            float4 a2 = *(const float4*)(s0 + 2 * VSTRIDE + 4 * c);
            float4 a3 = *(const float4*)(s0 + 3 * VSTRIDE + 4 * c);
            r0 = __fmaf_rn(a0.x, v.x, r0); r0 = __fmaf_rn(a0.y, v.y, r0);
            r0 = __fmaf_rn(a0.z, v.z, r0); r0 = __fmaf_rn(a0.w, v.w, r0);
            r1 = __fmaf_rn(a1.x, v.x, r1); r1 = __fmaf_rn(a1.y, v.y, r1);
            r1 = __fmaf_rn(a1.z, v.z, r1); r1 = __fmaf_rn(a1.w, v.w, r1);
            r2 = __fmaf_rn(a2.x, v.x, r2); r2 = __fmaf_rn(a2.y, v.y, r2);
            r2 = __fmaf_rn(a2.z, v.z, r2); r2 = __fmaf_rn(a2.w, v.w, r2);
            r3 = __fmaf_rn(a3.x, v.x, r3); r3 = __fmaf_rn(a3.y, v.y, r3);
            r3 = __fmaf_rn(a3.z, v.z, r3); r3 = __fmaf_rn(a3.w, v.w, r3);
        }
        float rec[4] = {r0, r1, r2, r3};

        // GEMM data for timestep t needed from here on (rec didn't need it).
        while (ld_acquire_gpu(&g_cnt[t]) < 16) __nanosleep(200);

        // ---- membrane updates (exact verified op order) ----
#pragma unroll
        for (int k = 0; k < 4; k++) {
            float gv    = gp[k][(size_t)t * BATCH * H];
            float cur1  = __fadd_rn(gv, b1h);
            float reset = (mem1[k] > 1.0f) ? 1.0f : 0.0f;
            float a     = __fmul_rn(0.9f, mem1[k]);
            a = __fadd_rn(a, cur1);
            a = __fadd_rn(a, rec[k]);
            a = __fadd_rn(a, bV1h);
            mem1[k] = __fsub_rn(a, reset);
            float spk = (mem1[k] > 1.0f) ? 1.0f : 0.0f;
            sf[(pw * ROWS_PB + 4 * g + k) * VSTRIDE + h] = spk;
        }
        __syncthreads();   // sf(t) visible; also orders next-step buffer reuse

        // ---- layer 2: warp 'wid' handles row 'wid', lanes 0..9 ----
        if (lane < OUT_N) {
            const float* w2r = W2s + lane * VSTRIDE;
            const float* sr  = sf + (pw * ROWS_PB + wid) * VSTRIDE;
            float c2 = 0.f;
#pragma unroll 8
            for (int c = 0; c < 32; c++) {
                float4 w = *(const float4*)(w2r + 4 * c);
                float4 s = *(const float4*)(sr + 4 * c);
                c2 = __fmaf_rn(s.x, w.x, c2); c2 = __fmaf_rn(s.y, w.y, c2);
                c2 = __fmaf_rn(s.z, w.z, c2); c2 = __fmaf_rn(s.w, w.w, c2);
            }
            float cur2 = __fadd_rn(c2, b2o);
            float rec2 = 0.f;
            const float* sp = sspk2 + (pr * ROWS_PB + wid) * SPK2_STRIDE;
#pragma unroll
            for (int p = 0; p < OUT_N; p++)
                rec2 = __fmaf_rn(sp[p], V2row[p], rec2);
            float reset2 = (mem2 > 1.0f) ? 1.0f : 0.0f;
            float u = __fmul_rn(0.9f, mem2);
            u = __fadd_rn(u, cur2);
            u = __fadd_rn(u, rec2);
            u = __fadd_rn(u, bV2o);
            mem2 = __fsub_rn(u, reset2);
            float s2 = (mem2 > 1.0f) ? 1.0f : 0.0f;
            ob[(size_t)t * BATCH * OUT_N] = s2;
            sspk2[(pw * ROWS_PB + wid) * SPK2_STRIDE + lane] = s2;
        }
        // next step's __syncthreads orders these writes vs later reads
    }
}

extern "C" void kernel_launch(void* const* d_in, const int* in_sizes, int n_in,
                              void* d_out, int out_size) {
    const float* x   = (const float*)d_in[0];
    const float* W1  = (const float*)d_in[1];
    const float* b1  = (const float*)d_in[2];
    const float* V1  = (const float*)d_in[3];
    const float* bV1 = (const float*)d_in[4];
    const float* W2  = (const float*)d_in[5];
    const float* b2  = (const float*)d_in[6];
    const float* V2  = (const float*)d_in[7];
    const float* bV2 = (const float*)d_in[8];
    float* out = (float*)d_out;

    cudaFuncSetAttribute(scan_kernel, cudaFuncAttributeMaxDynamicSharedMemorySize,
                         SCAN_SMEM_BYTES);

    // Zero the per-timestep completion counters (captured async memset).
    void* cnt_addr = nullptr;
    cudaGetSymbolAddress(&cnt_addr, g_cnt);
    cudaMemsetAsync(cnt_addr, 0, T_STEPS * sizeof(int), 0);

    // Fork a side stream for the scan so it can overlap the GEMM tail.
    cudaStream_t s2;
    cudaStreamCreateWithFlags(&s2, cudaStreamNonBlocking);
    cudaEvent_t eF, eJ;
    cudaEventCreateWithFlags(&eF, cudaEventDisableTiming);
    cudaEventCreateWithFlags(&eJ, cudaEventDisableTiming);

    cudaEventRecord(eF, 0);           // after memset on the capture stream
    cudaStreamWaitEvent(s2, eF, 0);

    const int M = T_STEPS * BATCH;    // 102400
    // GEMM launched FIRST: its 800 blocks dispatch ahead of the scan's (FIFO),
    // so the scan can never starve the GEMM -> no deadlock.
    gemm_xw1<<<M / 128, 256, 0, 0>>>(x, W1, M, D_IN);
    scan_kernel<<<BATCH / ROWS_PB, SCAN_THREADS, SCAN_SMEM_BYTES, s2>>>(
        b1, V1, bV1, W2, b2, V2, bV2, out);

    cudaEventRecord(eJ, s2);          // join scan back into the capture stream
    cudaStreamWaitEvent(0, eJ, 0);

    cudaEventDestroy(eF);
    cudaEventDestroy(eJ);
    cudaStreamDestroy(s2);
}

// round 12
// speedup vs baseline: 1.0001x; 1.0001x over previous
#include <cuda_runtime.h>

#define T_STEPS 50
#define BATCH   2048
#define D_IN    1156
#define H       128
#define OUT_N   10
#define KC      248          // Eigen kc (aarch64 default l1=16KB) -- verified exact

// Scratch: cur1[t][b][h] = (x[t,b,:] @ W1.T)[h]   (bias b1 added in scan)
__device__ float g_cur1[(size_t)T_STEPS * BATCH * H];  // 52.4 MB
// Per-timestep completion counters (16 GEMM tiles per timestep)
__device__ int g_cnt[T_STEPS];

__device__ __forceinline__ int ld_acquire_gpu(const int* p) {
    int v;
    asm volatile("ld.acquire.gpu.b32 %0, [%1];" : "=r"(v) : "l"(p) : "memory");
    return v;
}

// ---------------------------------------------------------------------------
// SGEMM emulating Eigen gebp (bit-exact, verified): KC=248 panels, each an
// ascending-k FMA chain per element, folded left-to-right in GMEM.
// 128x128 tile, BK=8, 256 threads, 8x8 micro-tile, double-buffered smem,
// 2 blocks/SM. At the FFMA issue floor (measured 844us). Signals g_cnt[t].
// ---------------------------------------------------------------------------
__global__ __launch_bounds__(256, 2)
void gemm_xw1(const float* __restrict__ A, const float* __restrict__ W, int M, int K) {
    const int BK = 8;
    __shared__ float As[2][BK][128];
    __shared__ float Bs[2][BK][128];

    int tid = threadIdx.x;
    int block_m = blockIdx.x * 128;
    int tx = tid & 15;
    int ty = tid >> 4;

    float acc[8][8];
#pragma unroll
    for (int i = 0; i < 8; i++)
#pragma unroll
        for (int j = 0; j < 8; j++) acc[i][j] = 0.f;

    int lRow = tid >> 1;
    int lCol = (tid & 1) * 4;
    const float* Aptr = A + (size_t)(block_m + lRow) * K;
    const float* Wptr = W + (size_t)lRow * K;

    const int NIT = (K + BK - 1) / BK;   // 145

    float4 av, wv;
    {   // fetch tile 0
        av = make_float4(0.f, 0.f, 0.f, 0.f);
        wv = make_float4(0.f, 0.f, 0.f, 0.f);
        if (lCol < K) {
            av = *(const float4*)(Aptr + lCol);
            wv = *(const float4*)(Wptr + lCol);
        }
        As[0][lCol + 0][lRow] = av.x; As[0][lCol + 1][lRow] = av.y;
        As[0][lCol + 2][lRow] = av.z; As[0][lCol + 3][lRow] = av.w;
        Bs[0][lCol + 0][lRow] = wv.x; Bs[0][lCol + 1][lRow] = wv.y;
        Bs[0][lCol + 2][lRow] = wv.z; Bs[0][lCol + 3][lRow] = wv.w;
    }
    __syncthreads();

    int panel_done = 0;
    float* cbase = g_cur1 + (size_t)(block_m + ty * 8) * H + tx * 8;

    for (int it = 0; it < NIT; it++) {
        int cur = it & 1;
        int nxt = cur ^ 1;

        if (it + 1 < NIT) {   // prefetch next tile while computing current
            int k0 = (it + 1) * BK;
            av = make_float4(0.f, 0.f, 0.f, 0.f);
            wv = make_float4(0.f, 0.f, 0.f, 0.f);
            if (k0 + lCol < K) {   // zero-pad tail; zeros are exact FMA no-ops
                av = *(const float4*)(Aptr + k0 + lCol);
                wv = *(const float4*)(Wptr + k0 + lCol);
            }
        }

#pragma unroll
        for (int kk = 0; kk < BK; kk++) {
            float ra[8], rb[8];
#pragma unroll
            for (int i = 0; i < 8; i++) ra[i] = As[cur][kk][ty * 8 + i];
#pragma unroll
            for (int j = 0; j < 8; j++) rb[j] = Bs[cur][kk][tx * 8 + j];
#pragma unroll
            for (int i = 0; i < 8; i++)
#pragma unroll
                for (int j = 0; j < 8; j++)
                    acc[i][j] = __fmaf_rn(ra[i], rb[j], acc[i][j]);
        }

        if (it + 1 < NIT) {
            As[nxt][lCol + 0][lRow] = av.x; As[nxt][lCol + 1][lRow] = av.y;
            As[nxt][lCol + 2][lRow] = av.z; As[nxt][lCol + 3][lRow] = av.w;
            Bs[nxt][lCol + 0][lRow] = wv.x; Bs[nxt][lCol + 1][lRow] = wv.y;
            Bs[nxt][lCol + 2][lRow] = wv.z; Bs[nxt][lCol + 3][lRow] = wv.w;
        }
        __syncthreads();

        // Eigen panel boundary: fold partial into C (gmem), left-to-right.
        int knext = (it + 1) * BK;
        if ((knext % KC) == 0 || knext >= K) {
            if (panel_done == 0) {
#pragma unroll
                for (int i = 0; i < 8; i++) {
                    float* crow = cbase + (size_t)i * H;
#pragma unroll
                    for (int j = 0; j < 8; j += 4)
                        *(float4*)(crow + j) = make_float4(acc[i][j], acc[i][j+1],
                                                           acc[i][j+2], acc[i][j+3]);
                }
            } else {
#pragma unroll
                for (int i = 0; i < 8; i++) {
                    float* crow = cbase + (size_t)i * H;
#pragma unroll
                    for (int j = 0; j < 8; j += 4) {
                        float4 c = *(float4*)(crow + j);
                        c.x = __fadd_rn(c.x, acc[i][j    ]);
                        c.y = __fadd_rn(c.y, acc[i][j + 1]);
                        c.z = __fadd_rn(c.z, acc[i][j + 2]);
                        c.w = __fadd_rn(c.w, acc[i][j + 3]);
                        *(float4*)(crow + j) = c;
                    }
                }
            }
            panel_done++;
#pragma unroll
            for (int i = 0; i < 8; i++)
#pragma unroll
                for (int j = 0; j < 8; j++) acc[i][j] = 0.f;
        }
    }

    // Signal: this tile (128 M-rows, all within one timestep) is complete.
    __threadfence();
    __syncthreads();
    if (tid == 0) atomicAdd(&g_cnt[block_m >> 11], 1);   // 2048 rows per t
}

// ---------------------------------------------------------------------------
// Dense-FMA LIF scan. 256 threads, 8 rows/block (2 groups x 4 rows), grid 256.
// Spikes stored as FLOATS in smem; rec/cur2 are dense ascending-j FMA chains
// with 0/1 multipliers -- bit-identical to the verified sparse-fadd chains
// (fma(1,v,a)=fadd(v,a); fma(0,v,a)=a; acc never -0). Static vectorized LDS,
// one __syncthreads per step, double-buffered spikes. Layer 2: one row/warp.
// ---------------------------------------------------------------------------
#define ROWS_PB 8
#define SCAN_THREADS 256
#define VSTRIDE 132                              // floats; 16B-aligned rows
#define V1S_ELEMS (128 * VSTRIDE)                // 16896
#define W2S_ELEMS (OUT_N * VSTRIDE)              // 1320
#define SF_ELEMS  (2 * ROWS_PB * VSTRIDE)        // 2112
#define SPK2_STRIDE 12
#define SPK2_ELEMS (2 * ROWS_PB * SPK2_STRIDE)   // 192
#define SCAN_SMEM_FLOATS (V1S_ELEMS + W2S_ELEMS + SF_ELEMS + SPK2_ELEMS)
#define SCAN_SMEM_BYTES (SCAN_SMEM_FLOATS * 4)

__global__ __launch_bounds__(SCAN_THREADS, 2)
void scan_kernel(const float* __restrict__ b1, const float* __restrict__ V1,
                 const float* __restrict__ bV1, const float* __restrict__ W2,
                 const float* __restrict__ b2, const float* __restrict__ V2,
                 const float* __restrict__ bV2, float* __restrict__ out) {
    extern __shared__ float smem[];
    float* V1s   = smem;                         // [h*132 + j] = V1[h][j]
    float* W2s   = smem + V1S_ELEMS;             // [o*132 + j]
    float* sf    = W2s + W2S_ELEMS;              // [(buf*8+lrow)*132 + h]
    float* sspk2 = sf + SF_ELEMS;                // [(buf*8+lrow)*12 + o]

    int tid  = threadIdx.x;
    int h    = tid & 127;
    int g    = tid >> 7;                         // group 0/1 -> rows 4g..4g+3
    int wid  = tid >> 5;                         // warp 0..7 -> layer-2 row wid
    int lane = tid & 31;
    int base = blockIdx.x * ROWS_PB;

    for (int idx = tid; idx < 128 * 128; idx += SCAN_THREADS)
        V1s[(idx >> 7) * VSTRIDE + (idx & 127)] = V1[idx];
    for (int idx = tid; idx < OUT_N * 128; idx += SCAN_THREADS)
        W2s[(idx >> 7) * VSTRIDE + (idx & 127)] = W2[idx];
    for (int idx = tid; idx < SF_ELEMS; idx += SCAN_THREADS) sf[idx] = 0.f;
    if (tid < SPK2_ELEMS) sspk2[tid] = 0.f;

    // Layer-2 per-lane constants (lanes 0..9 of each warp)
    float V2row[OUT_N];
    float b2o = 0.f, bV2o = 0.f, mem2 = 0.f;
    if (lane < OUT_N) {
#pragma unroll
        for (int p = 0; p < OUT_N; p++) V2row[p] = V2[lane * OUT_N + p];
        b2o = b2[lane]; bV2o = bV2[lane];
    }

    float b1h  = b1[h];
    float bV1h = bV1[h];
    float mem1[4] = {0.f, 0.f, 0.f, 0.f};
    const float* gp[4];
#pragma unroll
    for (int k = 0; k < 4; k++)
        gp[k] = g_cur1 + (size_t)(base + 4 * g + k) * H + h;
    float* ob = out + (size_t)(base + wid) * OUT_N + lane;
    const float* vrow = V1s + h * VSTRIDE;
    __syncthreads();

    for (int t = 0; t < T_STEPS; t++) {
        int pw = t & 1;
        int pr = pw ^ 1;

        // ---- layer 1 rec: dense ascending-j FMA chains, 4 rows share v4 ----
        float r0 = 0.f, r1 = 0.f, r2 = 0.f, r3 = 0.f;
        const float* s0 = sf + (pr * ROWS_PB + 4 * g) * VSTRIDE;
#pragma unroll 8
        for (int c = 0; c < 32; c++) {
            float4 v = *(const float4*)(vrow + 4 * c);
            float4 a0 = *(const float4*)(s0 + 4 * c);
            float4 a1 = *(const float4*)(s0 + VSTRIDE + 4 * c);
            float4 a2 = *(const float4*)(s0 + 2 * VSTRIDE + 4 * c);
            float4 a3 = *(const float4*)(s0 + 3 * VSTRIDE + 4 * c);
            r0 = __fmaf_rn(a0.x, v.x, r0); r0 = __fmaf_rn(a0.y, v.y, r0);
            r0 = __fmaf_rn(a0.z, v.z, r0); r0 = __fmaf_rn(a0.w, v.w, r0);
            r1 = __fmaf_rn(a1.x, v.x, r1); r1 = __fmaf_rn(a1.y, v.y, r1);
            r1 = __fmaf_rn(a1.z, v.z, r1); r1 = __fmaf_rn(a1.w, v.w, r1);
            r2 = __fmaf_rn(a2.x, v.x, r2); r2 = __fmaf_rn(a2.y, v.y, r2);
            r2 = __fmaf_rn(a2.z, v.z, r2); r2 = __fmaf_rn(a2.w, v.w, r2);
            r3 = __fmaf_rn(a3.x, v.x, r3); r3 = __fmaf_rn(a3.y, v.y, r3);
            r3 = __fmaf_rn(a3.z, v.z, r3); r3 = __fmaf_rn(a3.w, v.w, r3);
        }
        float rec[4] = {r0, r1, r2, r3};

        // GEMM data for timestep t needed from here on (rec didn't need it).
        while (ld_acquire_gpu(&g_cnt[t]) < 16) __nanosleep(200);

        // ---- membrane updates (exact verified op order) ----
#pragma unroll
        for (int k = 0; k < 4; k++) {
            float gv    = gp[k][(size_t)t * BATCH * H];
            float cur1  = __fadd_rn(gv, b1h);
            float reset = (mem1[k] > 1.0f) ? 1.0f : 0.0f;
            float a     = __fmul_rn(0.9f, mem1[k]);
            a = __fadd_rn(a, cur1);
            a = __fadd_rn(a, rec[k]);
            a = __fadd_rn(a, bV1h);
            mem1[k] = __fsub_rn(a, reset);
            float spk = (mem1[k] > 1.0f) ? 1.0f : 0.0f;
            sf[(pw * ROWS_PB + 4 * g + k) * VSTRIDE + h] = spk;
        }
        __syncthreads();   // sf(t) visible; also orders next-step buffer reuse

        // ---- layer 2: warp 'wid' handles row 'wid', lanes 0..9 ----
        if (lane < OUT_N) {
            const float* w2r = W2s + lane * VSTRIDE;
            const float* sr  = sf + (pw * ROWS_PB + wid) * VSTRIDE;
            float c2 = 0.f;
#pragma unroll 8
            for (int c = 0; c < 32; c++) {
                float4 w = *(const float4*)(w2r + 4 * c);
                float4 s = *(const float4*)(sr + 4 * c);
                c2 = __fmaf_rn(s.x, w.x, c2); c2 = __fmaf_rn(s.y, w.y, c2);
                c2 = __fmaf_rn(s.z, w.z, c2); c2 = __fmaf_rn(s.w, w.w, c2);
            }
            float cur2 = __fadd_rn(c2, b2o);
            float rec2 = 0.f;
            const float* sp = sspk2 + (pr * ROWS_PB + wid) * SPK2_STRIDE;
#pragma unroll
            for (int p = 0; p < OUT_N; p++)
                rec2 = __fmaf_rn(sp[p], V2row[p], rec2);
            float reset2 = (mem2 > 1.0f) ? 1.0f : 0.0f;
            float u = __fmul_rn(0.9f, mem2);
            u = __fadd_rn(u, cur2);
            u = __fadd_rn(u, rec2);
            u = __fadd_rn(u, bV2o);
            mem2 = __fsub_rn(u, reset2);
            float s2 = (mem2 > 1.0f) ? 1.0f : 0.0f;
            ob[(size_t)t * BATCH * OUT_N] = s2;
            sspk2[(pw * ROWS_PB + wid) * SPK2_STRIDE + lane] = s2;
        }
        // next step's __syncthreads orders these writes vs later reads
    }
}

extern "C" void kernel_launch(void* const* d_in, const int* in_sizes, int n_in,
                              void* d_out, int out_size) {
    const float* x   = (const float*)d_in[0];
    const float* W1  = (const float*)d_in[1];
    const float* b1  = (const float*)d_in[2];
    const float* V1  = (const float*)d_in[3];
    const float* bV1 = (const float*)d_in[4];
    const float* W2  = (const float*)d_in[5];
    const float* b2  = (const float*)d_in[6];
    const float* V2  = (const float*)d_in[7];
    const float* bV2 = (const float*)d_in[8];
    float* out = (float*)d_out;

    cudaFuncSetAttribute(scan_kernel, cudaFuncAttributeMaxDynamicSharedMemorySize,
                         SCAN_SMEM_BYTES);

    // Zero the per-timestep completion counters (captured async memset).
    void* cnt_addr = nullptr;
    cudaGetSymbolAddress(&cnt_addr, g_cnt);
    cudaMemsetAsync(cnt_addr, 0, T_STEPS * sizeof(int), 0);

    // Fork a side stream for the scan so it can overlap the GEMM tail.
    cudaStream_t s2;
    cudaStreamCreateWithFlags(&s2, cudaStreamNonBlocking);
    cudaEvent_t eF, eJ;
    cudaEventCreateWithFlags(&eF, cudaEventDisableTiming);
    cudaEventCreateWithFlags(&eJ, cudaEventDisableTiming);

    cudaEventRecord(eF, 0);           // after memset on the capture stream
    cudaStreamWaitEvent(s2, eF, 0);

    const int M = T_STEPS * BATCH;    // 102400
    // GEMM launched FIRST: its 800 blocks dispatch ahead of the scan's (FIFO),
    // so the scan can never starve the GEMM -> no deadlock.
    gemm_xw1<<<M / 128, 256, 0, 0>>>(x, W1, M, D_IN);
    scan_kernel<<<BATCH / ROWS_PB, SCAN_THREADS, SCAN_SMEM_BYTES, s2>>>(
        b1, V1, bV1, W2, b2, V2, bV2, out);

    cudaEventRecord(eJ, s2);          // join scan back into the capture stream
    cudaStreamWaitEvent(0, eJ, 0);

    cudaEventDestroy(eF);
    cudaEventDestroy(eJ);
    cudaStreamDestroy(s2);
}